// round 14
// baseline (speedup 1.0000x reference)
#include <cuda_runtime.h>
#include <cuda_bf16.h>
#include <cuda_fp16.h>
#include <math.h>
#include <stdint.h>

#define NN 4096
#define BB 64
#define DIN 64
#define DH 64
#define CC 128              // DIN + DH
#define EE 16
#define XGPITCH (BB * CC)   // 8192

// ================= device scratch (no runtime allocs) ==========================
__device__ __half g_Shi[(size_t)NN * NN];            // supports fp16 (A operand)
__device__ __half g_BXhi[(size_t)NN * NN];           // x^T fp16  [j=b*64+c][m]
__device__ __half g_BShi[(size_t)NN * NN];           // state^T / (z*state)^T fp16
__device__ __half g_XGhi[(size_t)NN * XGPITCH];      // S@CAT hi  [n][b*128+i] (fp16)
__device__ __half g_XGlo[(size_t)NN * XGPITCH];      // S@CAT lo  (fp16 residual)
__device__ __half g_Wg[(size_t)NN * CC * CC];        // gate W fp16 [n][i][o]
__device__ __half g_Wu[(size_t)NN * CC * DH];        // update W fp16 [n][i][o]
__device__ float g_ZR[(size_t)NN * XGPITCH];         // z_r [n][b*128+j] fp32

// ================= PTX helpers (sm_80-level only; NO tcgen05) ====================
__device__ __forceinline__ uint32_t smem_u32(const void* p) {
    uint32_t a;
    asm("{ .reg .u64 t; cvta.to.shared.u64 t, %1; cvt.u32.u64 %0, t; }" : "=r"(a) : "l"(p));
    return a;
}
__device__ __forceinline__ void cpa16(uint32_t dst, const void* src) {
    asm volatile("cp.async.cg.shared.global [%0], [%1], 16;" :: "r"(dst), "l"(src));
}
#define CP_COMMIT() asm volatile("cp.async.commit_group;" ::: "memory")
#define CP_WAIT1()  asm volatile("cp.async.wait_group 1;" ::: "memory")
#define CP_WAIT0()  asm volatile("cp.async.wait_group 0;" ::: "memory")

#define LDSM4(r0, r1, r2, r3, addr) \
    asm volatile("ldmatrix.sync.aligned.m8n8.x4.shared.b16 {%0,%1,%2,%3}, [%4];" \
        : "=r"(r0), "=r"(r1), "=r"(r2), "=r"(r3) : "r"(addr))

#define LDSM4T(r0, r1, r2, r3, addr) \
    asm volatile("ldmatrix.sync.aligned.m8n8.x4.trans.shared.b16 {%0,%1,%2,%3}, [%4];" \
        : "=r"(r0), "=r"(r1), "=r"(r2), "=r"(r3) : "r"(addr))

#define MMA_F16(c, a, b) \
    asm volatile("mma.sync.aligned.m16n8k16.row.col.f32.f16.f16.f32 " \
        "{%0,%1,%2,%3}, {%4,%5,%6,%7}, {%8,%9}, {%0,%1,%2,%3};" \
        : "+f"((c)[0]), "+f"((c)[1]), "+f"((c)[2]), "+f"((c)[3]) \
        : "r"((a)[0]), "r"((a)[1]), "r"((a)[2]), "r"((a)[3]), \
          "r"((b)[0]), "r"((b)[1]))

// ================ supports = softmax(relu(NE @ NE^T)) -> fp16 ====================
__global__ __launch_bounds__(256) void k_supports(const float* __restrict__ ne) {
    int n = blockIdx.x, tid = threadIdx.x;
    __shared__ float e[EE];
    __shared__ float redm[8], reds[8];
    if (tid < EE) e[tid] = ne[n * EE + tid];
    __syncthreads();

    float vals[16];
    float mx = 0.0f;
    #pragma unroll
    for (int j = 0; j < 16; j++) {
        int m = tid + j * 256;
        const float4* p = reinterpret_cast<const float4*>(ne + m * EE);
        float4 v0 = p[0], v1 = p[1], v2 = p[2], v3 = p[3];
        float d = e[0]*v0.x + e[1]*v0.y + e[2]*v0.z + e[3]*v0.w
                + e[4]*v1.x + e[5]*v1.y + e[6]*v1.z + e[7]*v1.w
                + e[8]*v2.x + e[9]*v2.y + e[10]*v2.z + e[11]*v2.w
                + e[12]*v3.x + e[13]*v3.y + e[14]*v3.z + e[15]*v3.w;
        d = fmaxf(d, 0.0f);
        vals[j] = d;
        mx = fmaxf(mx, d);
    }
    #pragma unroll
    for (int o = 16; o > 0; o >>= 1) mx = fmaxf(mx, __shfl_xor_sync(0xffffffffu, mx, o));
    if ((tid & 31) == 0) redm[tid >> 5] = mx;
    __syncthreads();
    mx = redm[0];
    #pragma unroll
    for (int w = 1; w < 8; w++) mx = fmaxf(mx, redm[w]);

    float s = 0.0f;
    #pragma unroll
    for (int j = 0; j < 16; j++) { vals[j] = __expf(vals[j] - mx); s += vals[j]; }
    #pragma unroll
    for (int o = 16; o > 0; o >>= 1) s += __shfl_xor_sync(0xffffffffu, s, o);
    if ((tid & 31) == 0) reds[tid >> 5] = s;
    __syncthreads();
    s = 0.0f;
    #pragma unroll
    for (int w = 0; w < 8; w++) s += reds[w];
    float inv = 1.0f / s;
    #pragma unroll
    for (int j = 0; j < 16; j++) {
        g_Shi[(size_t)n * NN + tid + j * 256] = __float2half_rn(vals[j] * inv);
    }
}

// ================ per-node weights -> single fp16, layout [n][i][o] ==============
__global__ __launch_bounds__(256) void k_mkw(const float* __restrict__ ne,
                                             const float* __restrict__ wp,
                                             __half* __restrict__ w,
                                             int IO) {
    int io = blockIdx.x * 256 + threadIdx.x;
    float wv[EE];
    #pragma unroll
    for (int d = 0; d < EE; d++) wv[d] = wp[(size_t)d * IO + io];
    __shared__ float sne[128 * EE];
    for (int n0 = 0; n0 < NN; n0 += 128) {
        __syncthreads();
        for (int t = threadIdx.x; t < 128 * EE; t += 256) sne[t] = ne[n0 * EE + t];
        __syncthreads();
        for (int nn = 0; nn < 128; nn++) {
            float v = 0.0f;
            #pragma unroll
            for (int d = 0; d < EE; d++) v += sne[nn * EE + d] * wv[d];
            w[(size_t)(n0 + nn) * IO + io] = __float2half_rn(v);
        }
    }
}

// ================ transpose -> fp16 (hi only): B operand build ===================
__global__ __launch_bounds__(256) void k_trans(const float* __restrict__ src,
                                               __half* __restrict__ dhi,
                                               int zmul) {
    __shared__ float tile[64][68];
    int b = blockIdx.y, m0 = blockIdx.x * 64, tid = threadIdx.x;
    #pragma unroll
    for (int i = 0; i < 4; i++) {
        int id = i * 256 + tid;
        int r = id >> 4, c4 = id & 15;
        float4 v = *reinterpret_cast<const float4*>(
            src + ((size_t)b * NN + m0 + r) * 64 + c4 * 4);
        if (zmul) {
            float4 z = *reinterpret_cast<const float4*>(
                g_ZR + (size_t)(m0 + r) * XGPITCH + b * CC + c4 * 4);
            v.x *= z.x; v.y *= z.y; v.z *= z.z; v.w *= z.w;
        }
        *reinterpret_cast<float4*>(&tile[r][c4 * 4]) = v;
    }
    __syncthreads();
    int c = tid >> 2, mg = (tid & 3) * 16;
    uint32_t hi[8];
    #pragma unroll
    for (int p = 0; p < 8; p++) {
        float v0 = tile[mg + 2 * p][c], v1 = tile[mg + 2 * p + 1][c];
        __half2 hp = __floats2half2_rn(v0, v1);
        hi[p] = *reinterpret_cast<uint32_t*>(&hp);
    }
    size_t o = (size_t)(b * 64 + c) * NN + m0 + mg;
    *reinterpret_cast<uint4*>(dhi + o)     = make_uint4(hi[0], hi[1], hi[2], hi[3]);
    *reinterpret_cast<uint4*>(dhi + o + 8) = make_uint4(hi[4], hi[5], hi[6], hi[7]);
}

// ================ big GEMM via mma.sync fp16, single term ========================
// C = S @ B^T. CTA 256(M)x128(N), K-chunk 32 (64B rows), 3-stage, 512 threads.
// 16 warps: 4(M) x 4(N), warptile 64x32 (same inner loop as the proven config).
#define OFF_B   16384                // A: 256 rows x 64 B
#define STAGE_BYTES 24576            // A 16K + B 8K
#define GEMM_SMEM (3 * STAGE_BYTES)  // 72 KB

__device__ __forceinline__ uint32_t swz64(int r, int c) {
    return (uint32_t)(r * 64 + ((c ^ (r & 3) ^ ((r >> 2) & 1)) << 4));
}
__device__ __forceinline__ uint32_t swz256(int r, int c) {
    return (uint32_t)(r * 256 + ((c ^ (r & 7)) << 4));
}
__device__ __forceinline__ uint32_t swz128(int r, int c) {
    return (uint32_t)(r * 128 + ((c ^ (r & 7)) << 4));
}

__device__ __forceinline__ void load_stage(uint32_t base, int kt, int tid,
        const __half* Ah, const __half* Bh) {
    int k0 = kt * 32;
    #pragma unroll
    for (int i = 0; i < 2; i++) {               // A: 256 rows x 4 chunks = 1024
        int id = i * 512 + tid;
        int r = id >> 2, c = id & 3;
        uint32_t off = swz64(r, c);
        cpa16(base + off, Ah + (size_t)r * NN + k0 + c * 8);
    }
    {                                           // B: 128 rows x 4 chunks = 512
        int r = tid >> 2, c = tid & 3;
        uint32_t off = swz64(r, c);
        cpa16(base + OFF_B + off, Bh + (size_t)r * NN + k0 + c * 8);
    }
    CP_COMMIT();
}

__global__ __launch_bounds__(512, 1) void k_hgemm(
        const __half* __restrict__ Bhi0,
        int coff0,
        const __half* __restrict__ Bhi1,
        int split) {
    extern __shared__ char dsm[];
    uint32_t sb = smem_u32(dsm);
    int tid = threadIdx.x, lane = tid & 31, wid = tid >> 5;
    int bn = blockIdx.x, bm = blockIdx.y;

    const __half* Bhp;
    int coff;
    if (bn < split) { Bhp = Bhi0; coff = coff0; }
    else            { Bhp = Bhi1; coff = 64; bn -= split; }

    const __half* Ah = g_Shi + (size_t)(bm * 256) * NN;
    const __half* Bh = Bhp + (size_t)(bn * 128) * NN;

    int warp_m = (wid >> 2) * 64;    // 4 warp-groups in M
    int warp_n = (wid & 3) * 32;     // 4 warps in N
    float acc[4][4][4] = {};

    load_stage(sb, 0, tid, Ah, Bh);
    load_stage(sb + STAGE_BYTES, 1, tid, Ah, Bh);

    const int NKT = NN / 32;
    int lrowA = lane & 15, lgrp = lane >> 4;

    for (int kt = 0; kt < NKT; kt++) {
        CP_WAIT1();
        __syncthreads();

        if (kt + 2 < NKT)
            load_stage(sb + ((kt + 2) % 3) * STAGE_BYTES, kt + 2, tid, Ah, Bh);
        else
            CP_COMMIT();

        uint32_t base = sb + (kt % 3) * STAGE_BYTES;
        #pragma unroll
        for (int s = 0; s < 2; s++) {
            int cb = s * 2 + lgrp;
            uint32_t bh[4][2];
            #pragma unroll
            for (int ng = 0; ng < 2; ng++) {
                int r = warp_n + ng * 16 + lrowA;
                uint32_t off = swz64(r, cb);
                uint32_t t0, t1, t2, t3;
                LDSM4(t0, t1, t2, t3, base + OFF_B + off);
                bh[ng * 2][0] = t0; bh[ng * 2][1] = t2;
                bh[ng * 2 + 1][0] = t1; bh[ng * 2 + 1][1] = t3;
            }
            #pragma unroll
            for (int mt = 0; mt < 4; mt++) {
                int r = warp_m + mt * 16 + lrowA;
                uint32_t off = swz64(r, cb);
                uint32_t ahi[4];
                LDSM4(ahi[0], ahi[1], ahi[2], ahi[3], base + off);
                #pragma unroll
                for (int nt = 0; nt < 4; nt++)
                    MMA_F16(acc[mt][nt], ahi, bh[nt]);
            }
        }
    }

    // epilogue: write XG as fp16 hi/lo pairs
    int row0 = bm * 256 + warp_m + (lane >> 2);
    #pragma unroll
    for (int mt = 0; mt < 4; mt++) {
        #pragma unroll
        for (int nt = 0; nt < 4; nt++) {
            int j = bn * 128 + warp_n + nt * 8 + (lane & 3) * 2;
            int b = j >> 6, c = j & 63;
            size_t p0 = (size_t)(row0 + mt * 16) * XGPITCH + b * CC + coff + c;
            size_t p1 = p0 + (size_t)8 * XGPITCH;
            float a0 = acc[mt][nt][0], a1 = acc[mt][nt][1];
            float a2 = acc[mt][nt][2], a3 = acc[mt][nt][3];
            __half h0 = __float2half_rn(a0), h1 = __float2half_rn(a1);
            __half h2 = __float2half_rn(a2), h3 = __float2half_rn(a3);
            __half2 h01 = __halves2half2(h0, h1);
            __half2 l01 = __floats2half2_rn(a0 - __half2float(h0), a1 - __half2float(h1));
            __half2 h23 = __halves2half2(h2, h3);
            __half2 l23 = __floats2half2_rn(a2 - __half2float(h2), a3 - __half2float(h3));
            *reinterpret_cast<__half2*>(g_XGhi + p0) = h01;
            *reinterpret_cast<__half2*>(g_XGlo + p0) = l01;
            *reinterpret_cast<__half2*>(g_XGhi + p1) = h23;
            *reinterpret_cast<__half2*>(g_XGlo + p1) = l23;
        }
    }
}

// ================ per-node gate GEMM (fp16 X hi/lo x fp16 W) + sigmoid ===========
// 8 warps: 2(M) x 4(N), warptile 32x32. X(64x128) @ W_n(128x128). 2 MMA terms.
#define NG_XHI 0
#define NG_XLO 16384
#define NG_W   32768
#define NG_BIAS 65536
#define NG_SMEM 66048

__global__ __launch_bounds__(256, 2) void k_ngate(const float* __restrict__ ne,
                                                  const float* __restrict__ gbp) {
    extern __shared__ char dsm[];
    uint32_t sb = smem_u32(dsm);
    int n = blockIdx.x, tid = threadIdx.x, lane = tid & 31, wid = tid >> 5;

    #pragma unroll
    for (int i = 0; i < 4; i++) {
        int id = i * 256 + tid;
        int r = id >> 4, c = id & 15;
        uint32_t off = swz256(r, c);
        size_t g = (size_t)n * XGPITCH + r * 128 + c * 8;
        cpa16(sb + NG_XHI + off, g_XGhi + g);
        cpa16(sb + NG_XLO + off, g_XGlo + g);
    }
    #pragma unroll
    for (int i = 0; i < 8; i++) {               // W: 128 rows x 16 chunks fp16
        int id = i * 256 + tid;
        int r = id >> 4, c = id & 15;
        uint32_t off = swz256(r, c);
        cpa16(sb + NG_W + off, g_Wg + (size_t)n * (CC * CC) + r * 128 + c * 8);
    }
    CP_COMMIT();

    if (tid < CC) {
        float v = 0.0f;
        #pragma unroll
        for (int d = 0; d < EE; d++) v += ne[n * EE + d] * gbp[d * CC + tid];
        reinterpret_cast<float*>(dsm + NG_BIAS)[tid] = v;
    }
    CP_WAIT0();
    __syncthreads();

    int warp_m = (wid >> 2) * 32;
    int warp_n = (wid & 3) * 32;
    int lrow = lane & 15, lgrp = lane >> 4;
    float acc[2][4][4] = {};

    #pragma unroll
    for (int k16 = 0; k16 < 8; k16++) {
        uint32_t bw[4][2];
        #pragma unroll
        for (int half = 0; half < 2; half++) {
            uint32_t off = swz256(k16 * 16 + lrow, (warp_n >> 3) + half * 2 + lgrp);
            uint32_t t0, t1, t2, t3;
            LDSM4T(t0, t1, t2, t3, sb + NG_W + off);
            bw[half * 2][0] = t0; bw[half * 2][1] = t1;
            bw[half * 2 + 1][0] = t2; bw[half * 2 + 1][1] = t3;
        }
        #pragma unroll
        for (int mt = 0; mt < 2; mt++) {
            uint32_t off = swz256(warp_m + mt * 16 + lrow, k16 * 2 + lgrp);
            uint32_t ah[4], al[4];
            LDSM4(ah[0], ah[1], ah[2], ah[3], sb + NG_XHI + off);
            LDSM4(al[0], al[1], al[2], al[3], sb + NG_XLO + off);
            #pragma unroll
            for (int nb = 0; nb < 4; nb++) {
                MMA_F16(acc[mt][nb], ah, bw[nb]);
                MMA_F16(acc[mt][nb], al, bw[nb]);
            }
        }
    }

    const float* biasp = reinterpret_cast<const float*>(dsm + NG_BIAS);
    #pragma unroll
    for (int mt = 0; mt < 2; mt++) {
        #pragma unroll
        for (int nb = 0; nb < 4; nb++) {
            int o = warp_n + nb * 8 + (lane & 3) * 2;
            int b = warp_m + mt * 16 + (lane >> 2);
            float b0 = biasp[o], b1 = biasp[o + 1];
            float y0 = 1.0f / (1.0f + __expf(-(acc[mt][nb][0] + b0)));
            float y1 = 1.0f / (1.0f + __expf(-(acc[mt][nb][1] + b1)));
            float y2 = 1.0f / (1.0f + __expf(-(acc[mt][nb][2] + b0)));
            float y3 = 1.0f / (1.0f + __expf(-(acc[mt][nb][3] + b1)));
            *reinterpret_cast<float2*>(g_ZR + (size_t)n * XGPITCH + b * CC + o) =
                make_float2(y0, y1);
            *reinterpret_cast<float2*>(g_ZR + (size_t)n * XGPITCH + (b + 8) * CC + o) =
                make_float2(y2, y3);
        }
    }
}

// ================ per-node update GEMM (fp16) + tanh + GRU combine ===============
#define NF_XHI 0
#define NF_XLO 16384
#define NF_W   32768
#define NF_BIAS 49152
#define NF_SMEM 49664

__global__ __launch_bounds__(256, 3) void k_nfinal(const float* __restrict__ ne,
                                                   const float* __restrict__ ubp,
                                                   const float* __restrict__ st,
                                                   float* __restrict__ out) {
    extern __shared__ char dsm[];
    uint32_t sb = smem_u32(dsm);
    int n = blockIdx.x, tid = threadIdx.x, lane = tid & 31, wid = tid >> 5;

    #pragma unroll
    for (int i = 0; i < 4; i++) {
        int id = i * 256 + tid;
        int r = id >> 4, c = id & 15;
        uint32_t off = swz256(r, c);
        size_t g = (size_t)n * XGPITCH + r * 128 + c * 8;
        cpa16(sb + NF_XHI + off, g_XGhi + g);
        cpa16(sb + NF_XLO + off, g_XGlo + g);
    }
    #pragma unroll
    for (int i = 0; i < 4; i++) {               // W: 128 rows x 8 chunks fp16
        int id = i * 256 + tid;
        int r = id >> 3, c = id & 7;
        uint32_t off = swz128(r, c);
        cpa16(sb + NF_W + off, g_Wu + (size_t)n * (CC * DH) + r * 64 + c * 8);
    }
    CP_COMMIT();

    if (tid < DH) {
        float v = 0.0f;
        #pragma unroll
        for (int d = 0; d < EE; d++) v += ne[n * EE + d] * ubp[d * DH + tid];
        reinterpret_cast<float*>(dsm + NF_BIAS)[tid] = v;
    }
    CP_WAIT0();
    __syncthreads();

    int warp_m = (wid >> 2) * 32;
    int warp_n = (wid & 3) * 16;
    int lrow = lane & 15, lgrp = lane >> 4;
    float acc[2][2][4] = {};

    #pragma unroll
    for (int k16 = 0; k16 < 8; k16++) {
        uint32_t bw[2][2];
        {
            uint32_t off = swz128(k16 * 16 + lrow, (warp_n >> 3) + lgrp);
            uint32_t t0, t1, t2, t3;
            LDSM4T(t0, t1, t2, t3, sb + NF_W + off);
            bw[0][0] = t0; bw[0][1] = t1;
            bw[1][0] = t2; bw[1][1] = t3;
        }
        #pragma unroll
        for (int mt = 0; mt < 2; mt++) {
            uint32_t off = swz256(warp_m + mt * 16 + lrow, k16 * 2 + lgrp);
            uint32_t ah[4], al[4];
            LDSM4(ah[0], ah[1], ah[2], ah[3], sb + NF_XHI + off);
            LDSM4(al[0], al[1], al[2], al[3], sb + NF_XLO + off);
            #pragma unroll
            for (int nb = 0; nb < 2; nb++) {
                MMA_F16(acc[mt][nb], ah, bw[nb]);
                MMA_F16(acc[mt][nb], al, bw[nb]);
            }
        }
    }

    const float* biasp = reinterpret_cast<const float*>(dsm + NF_BIAS);
    #pragma unroll
    for (int mt = 0; mt < 2; mt++) {
        #pragma unroll
        for (int nb = 0; nb < 2; nb++) {
            int o = warp_n + nb * 8 + (lane & 3) * 2;
            float b0 = biasp[o], b1 = biasp[o + 1];
            #pragma unroll
            for (int h = 0; h < 2; h++) {
                int b = warp_m + mt * 16 + (lane >> 2) + h * 8;
                float hc0 = tanhf(acc[mt][nb][h * 2] + b0);
                float hc1 = tanhf(acc[mt][nb][h * 2 + 1] + b1);
                float2 rr = *reinterpret_cast<const float2*>(
                    g_ZR + (size_t)n * XGPITCH + b * CC + DH + o);
                float2 ss = *reinterpret_cast<const float2*>(
                    st + ((size_t)b * NN + n) * DH + o);
                float2 hv;
                hv.x = rr.x * ss.x + (1.0f - rr.x) * hc0;
                hv.y = rr.y * ss.y + (1.0f - rr.y) * hc1;
                *reinterpret_cast<float2*>(out + ((size_t)b * NN + n) * DH + o) = hv;
            }
        }
    }
}

// ================ launch (multi-stream fork/join, capture-legal) =================
extern "C" void kernel_launch(void* const* d_in, const int* in_sizes, int n_in,
                              void* d_out, int out_size) {
    const float* x   = (const float*)d_in[0];
    const float* st  = (const float*)d_in[1];
    const float* ne  = (const float*)d_in[2];
    const float* gwp = (const float*)d_in[3];
    const float* gbp = (const float*)d_in[4];
    const float* uwp = (const float*)d_in[5];
    const float* ubp = (const float*)d_in[6];
    float* out = (float*)d_out;

    static cudaStream_t s1 = nullptr, s2 = nullptr;
    static cudaEvent_t e_fork, e_mkw, e_trans;
    static int initialized = 0;
    if (!initialized) {
        cudaFuncSetAttribute(k_hgemm,  cudaFuncAttributeMaxDynamicSharedMemorySize, GEMM_SMEM);
        cudaFuncSetAttribute(k_ngate,  cudaFuncAttributeMaxDynamicSharedMemorySize, NG_SMEM);
        cudaFuncSetAttribute(k_nfinal, cudaFuncAttributeMaxDynamicSharedMemorySize, NF_SMEM);
        cudaStreamCreateWithFlags(&s1, cudaStreamNonBlocking);
        cudaStreamCreateWithFlags(&s2, cudaStreamNonBlocking);
        cudaEventCreateWithFlags(&e_fork,  cudaEventDisableTiming);
        cudaEventCreateWithFlags(&e_mkw,   cudaEventDisableTiming);
        cudaEventCreateWithFlags(&e_trans, cudaEventDisableTiming);
        initialized = 1;
    }

    __half *bxh, *bsh, *wg, *wu;
    cudaGetSymbolAddress((void**)&bxh, g_BXhi);
    cudaGetSymbolAddress((void**)&bsh, g_BShi);
    cudaGetSymbolAddress((void**)&wg,  g_Wg);
    cudaGetSymbolAddress((void**)&wu,  g_Wu);

    // fork from default stream
    cudaEventRecord(e_fork, 0);
    cudaStreamWaitEvent(s1, e_fork, 0);
    cudaStreamWaitEvent(s2, e_fork, 0);

    // s1: per-node weight materialization (needed by k_ngate, much later)
    k_mkw<<<(CC * CC) / 256, 256, 0, s1>>>(ne, gwp, wg, CC * CC);
    k_mkw<<<(CC * DH) / 256, 256, 0, s1>>>(ne, uwp, wu, CC * DH);
    cudaEventRecord(e_mkw, s1);

    // s2: input transposes (needed by hgemm1), concurrent with k_supports
    k_trans<<<dim3(NN / 64, BB), 256, 0, s2>>>(x, bxh, 0);
    k_trans<<<dim3(NN / 64, BB), 256, 0, s2>>>(st, bsh, 0);
    cudaEventRecord(e_trans, s2);

    // default: supports, then join transposes before the merged GEMM
    k_supports<<<NN, 256>>>(ne);
    cudaStreamWaitEvent(0, e_trans, 0);

    // merged S@x | S@state : 1024 CTAs (256x128 tiles), 6.92 waves at 1 CTA/SM
    k_hgemm<<<dim3(2 * NN / 128, NN / 256), 512, GEMM_SMEM>>>(
        bxh, 0, bsh, NN / 128);

    // join weights before per-node gate GEMM
    cudaStreamWaitEvent(0, e_mkw, 0);
    k_ngate<<<NN, 256, NG_SMEM>>>(ne, gbp);

    // update path
    k_trans<<<dim3(NN / 64, BB), 256>>>(st, bsh, 1);        // (z*state)^T
    k_hgemm<<<dim3(NN / 128, NN / 256), 512, GEMM_SMEM>>>(
        bsh, 64, bsh, NN / 128);
    k_nfinal<<<NN, 256, NF_SMEM>>>(ne, ubp, st, out);
}

// round 15
// speedup vs baseline: 1.3160x; 1.3160x over previous
#include <cuda_runtime.h>
#include <cuda_bf16.h>
#include <cuda_fp16.h>
#include <math.h>
#include <stdint.h>

#define NN 4096
#define BB 64
#define DIN 64
#define DH 64
#define CC 128              // DIN + DH
#define EE 16
#define XGPITCH (BB * CC)   // 8192

// ================= device scratch (no runtime allocs) ==========================
__device__ __half g_Shi[(size_t)NN * NN];            // supports fp16 (A operand)
__device__ __half g_BXhi[(size_t)NN * NN];           // x^T fp16  [j=b*64+c][m]
__device__ __half g_BShi[(size_t)NN * NN];           // state^T / (z*state)^T fp16
__device__ __half g_XGhi[(size_t)NN * XGPITCH];      // S@CAT hi  [n][b*128+i] (fp16)
__device__ __half g_XGlo[(size_t)NN * XGPITCH];      // S@CAT lo  (fp16 residual)
__device__ __half g_Wg[(size_t)NN * CC * CC];        // gate W fp16 [n][i][o]
__device__ __half g_Wu[(size_t)NN * CC * DH];        // update W fp16 [n][i][o]
__device__ float g_ZR[(size_t)NN * XGPITCH];         // z_r [n][b*128+j] fp32

// ================= PTX helpers (sm_80-level only; NO tcgen05) ====================
__device__ __forceinline__ uint32_t smem_u32(const void* p) {
    uint32_t a;
    asm("{ .reg .u64 t; cvta.to.shared.u64 t, %1; cvt.u32.u64 %0, t; }" : "=r"(a) : "l"(p));
    return a;
}
__device__ __forceinline__ void cpa16(uint32_t dst, const void* src) {
    asm volatile("cp.async.cg.shared.global [%0], [%1], 16;" :: "r"(dst), "l"(src));
}
#define CP_COMMIT() asm volatile("cp.async.commit_group;" ::: "memory")
#define CP_WAIT1()  asm volatile("cp.async.wait_group 1;" ::: "memory")
#define CP_WAIT0()  asm volatile("cp.async.wait_group 0;" ::: "memory")

#define LDSM4(r0, r1, r2, r3, addr) \
    asm volatile("ldmatrix.sync.aligned.m8n8.x4.shared.b16 {%0,%1,%2,%3}, [%4];" \
        : "=r"(r0), "=r"(r1), "=r"(r2), "=r"(r3) : "r"(addr))

#define LDSM4T(r0, r1, r2, r3, addr) \
    asm volatile("ldmatrix.sync.aligned.m8n8.x4.trans.shared.b16 {%0,%1,%2,%3}, [%4];" \
        : "=r"(r0), "=r"(r1), "=r"(r2), "=r"(r3) : "r"(addr))

#define MMA_F16(c, a, b) \
    asm volatile("mma.sync.aligned.m16n8k16.row.col.f32.f16.f16.f32 " \
        "{%0,%1,%2,%3}, {%4,%5,%6,%7}, {%8,%9}, {%0,%1,%2,%3};" \
        : "+f"((c)[0]), "+f"((c)[1]), "+f"((c)[2]), "+f"((c)[3]) \
        : "r"((a)[0]), "r"((a)[1]), "r"((a)[2]), "r"((a)[3]), \
          "r"((b)[0]), "r"((b)[1]))

// ================ supports = softmax(relu(NE @ NE^T)) -> fp16 ====================
__global__ __launch_bounds__(256) void k_supports(const float* __restrict__ ne) {
    int n = blockIdx.x, tid = threadIdx.x;
    __shared__ float e[EE];
    __shared__ float redm[8], reds[8];
    if (tid < EE) e[tid] = ne[n * EE + tid];
    __syncthreads();

    float vals[16];
    float mx = 0.0f;
    #pragma unroll
    for (int j = 0; j < 16; j++) {
        int m = tid + j * 256;
        const float4* p = reinterpret_cast<const float4*>(ne + m * EE);
        float4 v0 = p[0], v1 = p[1], v2 = p[2], v3 = p[3];
        float d = e[0]*v0.x + e[1]*v0.y + e[2]*v0.z + e[3]*v0.w
                + e[4]*v1.x + e[5]*v1.y + e[6]*v1.z + e[7]*v1.w
                + e[8]*v2.x + e[9]*v2.y + e[10]*v2.z + e[11]*v2.w
                + e[12]*v3.x + e[13]*v3.y + e[14]*v3.z + e[15]*v3.w;
        d = fmaxf(d, 0.0f);
        vals[j] = d;
        mx = fmaxf(mx, d);
    }
    #pragma unroll
    for (int o = 16; o > 0; o >>= 1) mx = fmaxf(mx, __shfl_xor_sync(0xffffffffu, mx, o));
    if ((tid & 31) == 0) redm[tid >> 5] = mx;
    __syncthreads();
    mx = redm[0];
    #pragma unroll
    for (int w = 1; w < 8; w++) mx = fmaxf(mx, redm[w]);

    float s = 0.0f;
    #pragma unroll
    for (int j = 0; j < 16; j++) { vals[j] = __expf(vals[j] - mx); s += vals[j]; }
    #pragma unroll
    for (int o = 16; o > 0; o >>= 1) s += __shfl_xor_sync(0xffffffffu, s, o);
    if ((tid & 31) == 0) reds[tid >> 5] = s;
    __syncthreads();
    s = 0.0f;
    #pragma unroll
    for (int w = 0; w < 8; w++) s += reds[w];
    float inv = 1.0f / s;
    #pragma unroll
    for (int j = 0; j < 16; j++) {
        g_Shi[(size_t)n * NN + tid + j * 256] = __float2half_rn(vals[j] * inv);
    }
}

// ================ per-node weights -> single fp16, layout [n][i][o] ==============
__global__ __launch_bounds__(256) void k_mkw(const float* __restrict__ ne,
                                             const float* __restrict__ wp,
                                             __half* __restrict__ w,
                                             int IO) {
    int io = blockIdx.x * 256 + threadIdx.x;
    float wv[EE];
    #pragma unroll
    for (int d = 0; d < EE; d++) wv[d] = wp[(size_t)d * IO + io];
    __shared__ float sne[128 * EE];
    for (int n0 = 0; n0 < NN; n0 += 128) {
        __syncthreads();
        for (int t = threadIdx.x; t < 128 * EE; t += 256) sne[t] = ne[n0 * EE + t];
        __syncthreads();
        for (int nn = 0; nn < 128; nn++) {
            float v = 0.0f;
            #pragma unroll
            for (int d = 0; d < EE; d++) v += sne[nn * EE + d] * wv[d];
            w[(size_t)(n0 + nn) * IO + io] = __float2half_rn(v);
        }
    }
}

// ================ transpose -> fp16 (hi only): B operand build ===================
__global__ __launch_bounds__(256) void k_trans(const float* __restrict__ src,
                                               __half* __restrict__ dhi,
                                               int zmul) {
    __shared__ float tile[64][68];
    int b = blockIdx.y, m0 = blockIdx.x * 64, tid = threadIdx.x;
    #pragma unroll
    for (int i = 0; i < 4; i++) {
        int id = i * 256 + tid;
        int r = id >> 4, c4 = id & 15;
        float4 v = *reinterpret_cast<const float4*>(
            src + ((size_t)b * NN + m0 + r) * 64 + c4 * 4);
        if (zmul) {
            float4 z = *reinterpret_cast<const float4*>(
                g_ZR + (size_t)(m0 + r) * XGPITCH + b * CC + c4 * 4);
            v.x *= z.x; v.y *= z.y; v.z *= z.z; v.w *= z.w;
        }
        *reinterpret_cast<float4*>(&tile[r][c4 * 4]) = v;
    }
    __syncthreads();
    int c = tid >> 2, mg = (tid & 3) * 16;
    uint32_t hi[8];
    #pragma unroll
    for (int p = 0; p < 8; p++) {
        float v0 = tile[mg + 2 * p][c], v1 = tile[mg + 2 * p + 1][c];
        __half2 hp = __floats2half2_rn(v0, v1);
        hi[p] = *reinterpret_cast<uint32_t*>(&hp);
    }
    size_t o = (size_t)(b * 64 + c) * NN + m0 + mg;
    *reinterpret_cast<uint4*>(dhi + o)     = make_uint4(hi[0], hi[1], hi[2], hi[3]);
    *reinterpret_cast<uint4*>(dhi + o + 8) = make_uint4(hi[4], hi[5], hi[6], hi[7]);
}

// ================ big GEMM via mma.sync fp16, single term ========================
// C = S @ B^T. CTA 128x128, K-chunk 32 (64B rows), 3-stage, 2 CTAs/SM.
// (R13-proven configuration.)
#define OFF_B   8192
#define STAGE_BYTES 16384
#define GEMM_SMEM (3 * STAGE_BYTES)  // 48 KB

__device__ __forceinline__ uint32_t swz64(int r, int c) {
    return (uint32_t)(r * 64 + ((c ^ (r & 3) ^ ((r >> 2) & 1)) << 4));
}
__device__ __forceinline__ uint32_t swz256(int r, int c) {
    return (uint32_t)(r * 256 + ((c ^ (r & 7)) << 4));
}
__device__ __forceinline__ uint32_t swz128(int r, int c) {
    return (uint32_t)(r * 128 + ((c ^ (r & 7)) << 4));
}

__device__ __forceinline__ void load_stage(uint32_t base, int kt, int tid,
        const __half* Ah, const __half* Bh) {
    int k0 = kt * 32;
    #pragma unroll
    for (int i = 0; i < 2; i++) {
        int id = i * 256 + tid;
        int r = id >> 2, c = id & 3;
        uint32_t off = swz64(r, c);
        size_t g = (size_t)r * NN + k0 + c * 8;
        cpa16(base + off,         Ah + g);
        cpa16(base + OFF_B + off, Bh + g);
    }
    CP_COMMIT();
}

__global__ __launch_bounds__(256, 2) void k_hgemm(
        const __half* __restrict__ Bhi0,
        int coff0,
        const __half* __restrict__ Bhi1,
        int split) {
    extern __shared__ char dsm[];
    uint32_t sb = smem_u32(dsm);
    int tid = threadIdx.x, lane = tid & 31, wid = tid >> 5;
    int bn = blockIdx.x, bm = blockIdx.y;

    const __half* Bhp;
    int coff;
    if (bn < split) { Bhp = Bhi0; coff = coff0; }
    else            { Bhp = Bhi1; coff = 64; bn -= split; }

    const __half* Ah = g_Shi + (size_t)(bm * 128) * NN;
    const __half* Bh = Bhp + (size_t)(bn * 128) * NN;

    int warp_m = (wid >> 2) * 64;
    int warp_n = (wid & 3) * 32;
    float acc[4][4][4] = {};

    load_stage(sb, 0, tid, Ah, Bh);
    load_stage(sb + STAGE_BYTES, 1, tid, Ah, Bh);

    const int NKT = NN / 32;
    int lrowA = lane & 15, lgrp = lane >> 4;

    for (int kt = 0; kt < NKT; kt++) {
        CP_WAIT1();
        __syncthreads();

        if (kt + 2 < NKT)
            load_stage(sb + ((kt + 2) % 3) * STAGE_BYTES, kt + 2, tid, Ah, Bh);
        else
            CP_COMMIT();

        uint32_t base = sb + (kt % 3) * STAGE_BYTES;
        #pragma unroll
        for (int s = 0; s < 2; s++) {
            int cb = s * 2 + lgrp;
            uint32_t bh[4][2];
            #pragma unroll
            for (int ng = 0; ng < 2; ng++) {
                int r = warp_n + ng * 16 + lrowA;
                uint32_t off = swz64(r, cb);
                uint32_t t0, t1, t2, t3;
                LDSM4(t0, t1, t2, t3, base + OFF_B + off);
                bh[ng * 2][0] = t0; bh[ng * 2][1] = t2;
                bh[ng * 2 + 1][0] = t1; bh[ng * 2 + 1][1] = t3;
            }
            #pragma unroll
            for (int mt = 0; mt < 4; mt++) {
                int r = warp_m + mt * 16 + lrowA;
                uint32_t off = swz64(r, cb);
                uint32_t ahi[4];
                LDSM4(ahi[0], ahi[1], ahi[2], ahi[3], base + off);
                #pragma unroll
                for (int nt = 0; nt < 4; nt++)
                    MMA_F16(acc[mt][nt], ahi, bh[nt]);
            }
        }
    }

    // epilogue: write XG as fp16 hi/lo pairs
    int row0 = bm * 128 + warp_m + (lane >> 2);
    #pragma unroll
    for (int mt = 0; mt < 4; mt++) {
        #pragma unroll
        for (int nt = 0; nt < 4; nt++) {
            int j = bn * 128 + warp_n + nt * 8 + (lane & 3) * 2;
            int b = j >> 6, c = j & 63;
            size_t p0 = (size_t)(row0 + mt * 16) * XGPITCH + b * CC + coff + c;
            size_t p1 = p0 + (size_t)8 * XGPITCH;
            float a0 = acc[mt][nt][0], a1 = acc[mt][nt][1];
            float a2 = acc[mt][nt][2], a3 = acc[mt][nt][3];
            __half h0 = __float2half_rn(a0), h1 = __float2half_rn(a1);
            __half h2 = __float2half_rn(a2), h3 = __float2half_rn(a3);
            __half2 h01 = __halves2half2(h0, h1);
            __half2 l01 = __floats2half2_rn(a0 - __half2float(h0), a1 - __half2float(h1));
            __half2 h23 = __halves2half2(h2, h3);
            __half2 l23 = __floats2half2_rn(a2 - __half2float(h2), a3 - __half2float(h3));
            *reinterpret_cast<__half2*>(g_XGhi + p0) = h01;
            *reinterpret_cast<__half2*>(g_XGlo + p0) = l01;
            *reinterpret_cast<__half2*>(g_XGhi + p1) = h23;
            *reinterpret_cast<__half2*>(g_XGlo + p1) = l23;
        }
    }
}

// ================ per-node gate GEMM (fp16 X hi/lo x fp16 W) + sigmoid ===========
#define NG_XHI 0
#define NG_XLO 16384
#define NG_W   32768
#define NG_BIAS 65536
#define NG_SMEM 66048

__global__ __launch_bounds__(256, 2) void k_ngate(const float* __restrict__ ne,
                                                  const float* __restrict__ gbp) {
    extern __shared__ char dsm[];
    uint32_t sb = smem_u32(dsm);
    int n = blockIdx.x, tid = threadIdx.x, lane = tid & 31, wid = tid >> 5;

    #pragma unroll
    for (int i = 0; i < 4; i++) {
        int id = i * 256 + tid;
        int r = id >> 4, c = id & 15;
        uint32_t off = swz256(r, c);
        size_t g = (size_t)n * XGPITCH + r * 128 + c * 8;
        cpa16(sb + NG_XHI + off, g_XGhi + g);
        cpa16(sb + NG_XLO + off, g_XGlo + g);
    }
    #pragma unroll
    for (int i = 0; i < 8; i++) {
        int id = i * 256 + tid;
        int r = id >> 4, c = id & 15;
        uint32_t off = swz256(r, c);
        cpa16(sb + NG_W + off, g_Wg + (size_t)n * (CC * CC) + r * 128 + c * 8);
    }
    CP_COMMIT();

    if (tid < CC) {
        float v = 0.0f;
        #pragma unroll
        for (int d = 0; d < EE; d++) v += ne[n * EE + d] * gbp[d * CC + tid];
        reinterpret_cast<float*>(dsm + NG_BIAS)[tid] = v;
    }
    CP_WAIT0();
    __syncthreads();

    int warp_m = (wid >> 2) * 32;
    int warp_n = (wid & 3) * 32;
    int lrow = lane & 15, lgrp = lane >> 4;
    float acc[2][4][4] = {};

    #pragma unroll
    for (int k16 = 0; k16 < 8; k16++) {
        uint32_t bw[4][2];
        #pragma unroll
        for (int half = 0; half < 2; half++) {
            uint32_t off = swz256(k16 * 16 + lrow, (warp_n >> 3) + half * 2 + lgrp);
            uint32_t t0, t1, t2, t3;
            LDSM4T(t0, t1, t2, t3, sb + NG_W + off);
            bw[half * 2][0] = t0; bw[half * 2][1] = t1;
            bw[half * 2 + 1][0] = t2; bw[half * 2 + 1][1] = t3;
        }
        #pragma unroll
        for (int mt = 0; mt < 2; mt++) {
            uint32_t off = swz256(warp_m + mt * 16 + lrow, k16 * 2 + lgrp);
            uint32_t ah[4], al[4];
            LDSM4(ah[0], ah[1], ah[2], ah[3], sb + NG_XHI + off);
            LDSM4(al[0], al[1], al[2], al[3], sb + NG_XLO + off);
            #pragma unroll
            for (int nb = 0; nb < 4; nb++) {
                MMA_F16(acc[mt][nb], ah, bw[nb]);
                MMA_F16(acc[mt][nb], al, bw[nb]);
            }
        }
    }

    const float* biasp = reinterpret_cast<const float*>(dsm + NG_BIAS);
    #pragma unroll
    for (int mt = 0; mt < 2; mt++) {
        #pragma unroll
        for (int nb = 0; nb < 4; nb++) {
            int o = warp_n + nb * 8 + (lane & 3) * 2;
            int b = warp_m + mt * 16 + (lane >> 2);
            float b0 = biasp[o], b1 = biasp[o + 1];
            float y0 = 1.0f / (1.0f + __expf(-(acc[mt][nb][0] + b0)));
            float y1 = 1.0f / (1.0f + __expf(-(acc[mt][nb][1] + b1)));
            float y2 = 1.0f / (1.0f + __expf(-(acc[mt][nb][2] + b0)));
            float y3 = 1.0f / (1.0f + __expf(-(acc[mt][nb][3] + b1)));
            *reinterpret_cast<float2*>(g_ZR + (size_t)n * XGPITCH + b * CC + o) =
                make_float2(y0, y1);
            *reinterpret_cast<float2*>(g_ZR + (size_t)n * XGPITCH + (b + 8) * CC + o) =
                make_float2(y2, y3);
        }
    }
}

// ================ per-node update GEMM (fp16) + tanh + GRU combine ===============
#define NF_XHI 0
#define NF_XLO 16384
#define NF_W   32768
#define NF_BIAS 49152
#define NF_SMEM 49664

__global__ __launch_bounds__(256, 3) void k_nfinal(const float* __restrict__ ne,
                                                   const float* __restrict__ ubp,
                                                   const float* __restrict__ st,
                                                   float* __restrict__ out) {
    extern __shared__ char dsm[];
    uint32_t sb = smem_u32(dsm);
    int n = blockIdx.x, tid = threadIdx.x, lane = tid & 31, wid = tid >> 5;

    #pragma unroll
    for (int i = 0; i < 4; i++) {
        int id = i * 256 + tid;
        int r = id >> 4, c = id & 15;
        uint32_t off = swz256(r, c);
        size_t g = (size_t)n * XGPITCH + r * 128 + c * 8;
        cpa16(sb + NF_XHI + off, g_XGhi + g);
        cpa16(sb + NF_XLO + off, g_XGlo + g);
    }
    #pragma unroll
    for (int i = 0; i < 4; i++) {
        int id = i * 256 + tid;
        int r = id >> 3, c = id & 7;
        uint32_t off = swz128(r, c);
        cpa16(sb + NF_W + off, g_Wu + (size_t)n * (CC * DH) + r * 64 + c * 8);
    }
    CP_COMMIT();

    if (tid < DH) {
        float v = 0.0f;
        #pragma unroll
        for (int d = 0; d < EE; d++) v += ne[n * EE + d] * ubp[d * DH + tid];
        reinterpret_cast<float*>(dsm + NF_BIAS)[tid] = v;
    }
    CP_WAIT0();
    __syncthreads();

    int warp_m = (wid >> 2) * 32;
    int warp_n = (wid & 3) * 16;
    int lrow = lane & 15, lgrp = lane >> 4;
    float acc[2][2][4] = {};

    #pragma unroll
    for (int k16 = 0; k16 < 8; k16++) {
        uint32_t bw[2][2];
        {
            uint32_t off = swz128(k16 * 16 + lrow, (warp_n >> 3) + lgrp);
            uint32_t t0, t1, t2, t3;
            LDSM4T(t0, t1, t2, t3, sb + NF_W + off);
            bw[0][0] = t0; bw[0][1] = t1;
            bw[1][0] = t2; bw[1][1] = t3;
        }
        #pragma unroll
        for (int mt = 0; mt < 2; mt++) {
            uint32_t off = swz256(warp_m + mt * 16 + lrow, k16 * 2 + lgrp);
            uint32_t ah[4], al[4];
            LDSM4(ah[0], ah[1], ah[2], ah[3], sb + NF_XHI + off);
            LDSM4(al[0], al[1], al[2], al[3], sb + NF_XLO + off);
            #pragma unroll
            for (int nb = 0; nb < 2; nb++) {
                MMA_F16(acc[mt][nb], ah, bw[nb]);
                MMA_F16(acc[mt][nb], al, bw[nb]);
            }
        }
    }

    const float* biasp = reinterpret_cast<const float*>(dsm + NF_BIAS);
    #pragma unroll
    for (int mt = 0; mt < 2; mt++) {
        #pragma unroll
        for (int nb = 0; nb < 2; nb++) {
            int o = warp_n + nb * 8 + (lane & 3) * 2;
            float b0 = biasp[o], b1 = biasp[o + 1];
            #pragma unroll
            for (int h = 0; h < 2; h++) {
                int b = warp_m + mt * 16 + (lane >> 2) + h * 8;
                float hc0 = tanhf(acc[mt][nb][h * 2] + b0);
                float hc1 = tanhf(acc[mt][nb][h * 2 + 1] + b1);
                float2 rr = *reinterpret_cast<const float2*>(
                    g_ZR + (size_t)n * XGPITCH + b * CC + DH + o);
                float2 ss = *reinterpret_cast<const float2*>(
                    st + ((size_t)b * NN + n) * DH + o);
                float2 hv;
                hv.x = rr.x * ss.x + (1.0f - rr.x) * hc0;
                hv.y = rr.y * ss.y + (1.0f - rr.y) * hc1;
                *reinterpret_cast<float2*>(out + ((size_t)b * NN + n) * DH + o) = hv;
            }
        }
    }
}

// ================ launch (multi-stream fork/join, capture-legal) =================
extern "C" void kernel_launch(void* const* d_in, const int* in_sizes, int n_in,
                              void* d_out, int out_size) {
    const float* x   = (const float*)d_in[0];
    const float* st  = (const float*)d_in[1];
    const float* ne  = (const float*)d_in[2];
    const float* gwp = (const float*)d_in[3];
    const float* gbp = (const float*)d_in[4];
    const float* uwp = (const float*)d_in[5];
    const float* ubp = (const float*)d_in[6];
    float* out = (float*)d_out;

    static cudaStream_t s1 = nullptr, s2 = nullptr;
    static cudaEvent_t e_fork, e_mkw, e_trans;
    static int initialized = 0;
    if (!initialized) {
        cudaFuncSetAttribute(k_hgemm,  cudaFuncAttributeMaxDynamicSharedMemorySize, GEMM_SMEM);
        cudaFuncSetAttribute(k_ngate,  cudaFuncAttributeMaxDynamicSharedMemorySize, NG_SMEM);
        cudaFuncSetAttribute(k_nfinal, cudaFuncAttributeMaxDynamicSharedMemorySize, NF_SMEM);
        cudaStreamCreateWithFlags(&s1, cudaStreamNonBlocking);
        cudaStreamCreateWithFlags(&s2, cudaStreamNonBlocking);
        cudaEventCreateWithFlags(&e_fork,  cudaEventDisableTiming);
        cudaEventCreateWithFlags(&e_mkw,   cudaEventDisableTiming);
        cudaEventCreateWithFlags(&e_trans, cudaEventDisableTiming);
        initialized = 1;
    }

    __half *bxh, *bsh, *wg, *wu;
    cudaGetSymbolAddress((void**)&bxh, g_BXhi);
    cudaGetSymbolAddress((void**)&bsh, g_BShi);
    cudaGetSymbolAddress((void**)&wg,  g_Wg);
    cudaGetSymbolAddress((void**)&wu,  g_Wu);

    // fork from default stream
    cudaEventRecord(e_fork, 0);
    cudaStreamWaitEvent(s1, e_fork, 0);
    cudaStreamWaitEvent(s2, e_fork, 0);

    // s1: per-node weight materialization (needed by k_ngate, much later)
    k_mkw<<<(CC * CC) / 256, 256, 0, s1>>>(ne, gwp, wg, CC * CC);
    k_mkw<<<(CC * DH) / 256, 256, 0, s1>>>(ne, uwp, wu, CC * DH);
    cudaEventRecord(e_mkw, s1);

    // s2: input transposes (needed by hgemm1), concurrent with k_supports
    k_trans<<<dim3(NN / 64, BB), 256, 0, s2>>>(x, bxh, 0);
    k_trans<<<dim3(NN / 64, BB), 256, 0, s2>>>(st, bsh, 0);
    cudaEventRecord(e_trans, s2);

    // default: supports, then join transposes before the merged GEMM
    k_supports<<<NN, 256>>>(ne);
    cudaStreamWaitEvent(0, e_trans, 0);

    // merged S@x | S@state : 2048 CTAs (128x128 tiles), 2 CTAs/SM
    k_hgemm<<<dim3(2 * NN / 128, NN / 128), 256, GEMM_SMEM>>>(
        bxh, 0, bsh, NN / 128);

    // join weights before per-node gate GEMM
    cudaStreamWaitEvent(0, e_mkw, 0);
    k_ngate<<<NN, 256, NG_SMEM>>>(ne, gbp);

    // update path
    k_trans<<<dim3(NN / 64, BB), 256>>>(st, bsh, 1);        // (z*state)^T
    k_hgemm<<<dim3(NN / 128, NN / 128), 256, GEMM_SMEM>>>(
        bsh, 64, bsh, NN / 128);
    k_nfinal<<<NN, 256, NF_SMEM>>>(ne, ubp, st, out);
}

// round 16
// speedup vs baseline: 1.4082x; 1.0701x over previous
#include <cuda_runtime.h>
#include <cuda_bf16.h>
#include <cuda_fp16.h>
#include <math.h>
#include <stdint.h>

#define NN 4096
#define BB 64
#define DIN 64
#define DH 64
#define CC 128              // DIN + DH
#define EE 16
#define XGPITCH (BB * CC)   // 8192

// ================= device scratch (no runtime allocs) ==========================
__device__ __half g_Shi[(size_t)NN * NN];            // supports fp16 (A operand)
__device__ __half g_BXhi[(size_t)NN * NN];           // x^T fp16  [j=b*64+c][m]
__device__ __half g_BShi[(size_t)NN * NN];           // state^T / (z*state)^T fp16
__device__ __half g_XG[(size_t)NN * XGPITCH];        // S@CAT fp16 [n][b*128+i]
__device__ __half g_Wg[(size_t)NN * CC * CC];        // gate W fp16 [n][i][o]
__device__ __half g_Wu[(size_t)NN * CC * DH];        // update W fp16 [n][i][o]
__device__ float g_ZR[(size_t)NN * XGPITCH];         // z_r [n][b*128+j] fp32

// ================= PTX helpers (sm_80-level only; NO tcgen05) ====================
__device__ __forceinline__ uint32_t smem_u32(const void* p) {
    uint32_t a;
    asm("{ .reg .u64 t; cvta.to.shared.u64 t, %1; cvt.u32.u64 %0, t; }" : "=r"(a) : "l"(p));
    return a;
}
__device__ __forceinline__ void cpa16(uint32_t dst, const void* src) {
    asm volatile("cp.async.cg.shared.global [%0], [%1], 16;" :: "r"(dst), "l"(src));
}
#define CP_COMMIT() asm volatile("cp.async.commit_group;" ::: "memory")
#define CP_WAIT1()  asm volatile("cp.async.wait_group 1;" ::: "memory")
#define CP_WAIT0()  asm volatile("cp.async.wait_group 0;" ::: "memory")

#define LDSM4(r0, r1, r2, r3, addr) \
    asm volatile("ldmatrix.sync.aligned.m8n8.x4.shared.b16 {%0,%1,%2,%3}, [%4];" \
        : "=r"(r0), "=r"(r1), "=r"(r2), "=r"(r3) : "r"(addr))

#define LDSM4T(r0, r1, r2, r3, addr) \
    asm volatile("ldmatrix.sync.aligned.m8n8.x4.trans.shared.b16 {%0,%1,%2,%3}, [%4];" \
        : "=r"(r0), "=r"(r1), "=r"(r2), "=r"(r3) : "r"(addr))

#define MMA_F16(c, a, b) \
    asm volatile("mma.sync.aligned.m16n8k16.row.col.f32.f16.f16.f32 " \
        "{%0,%1,%2,%3}, {%4,%5,%6,%7}, {%8,%9}, {%0,%1,%2,%3};" \
        : "+f"((c)[0]), "+f"((c)[1]), "+f"((c)[2]), "+f"((c)[3]) \
        : "r"((a)[0]), "r"((a)[1]), "r"((a)[2]), "r"((a)[3]), \
          "r"((b)[0]), "r"((b)[1]))

// ================ supports = softmax(relu(NE @ NE^T)) -> fp16 ====================
__global__ __launch_bounds__(256) void k_supports(const float* __restrict__ ne) {
    int n = blockIdx.x, tid = threadIdx.x;
    __shared__ float e[EE];
    __shared__ float redm[8], reds[8];
    if (tid < EE) e[tid] = ne[n * EE + tid];
    __syncthreads();

    float vals[16];
    float mx = 0.0f;
    #pragma unroll
    for (int j = 0; j < 16; j++) {
        int m = tid + j * 256;
        const float4* p = reinterpret_cast<const float4*>(ne + m * EE);
        float4 v0 = p[0], v1 = p[1], v2 = p[2], v3 = p[3];
        float d = e[0]*v0.x + e[1]*v0.y + e[2]*v0.z + e[3]*v0.w
                + e[4]*v1.x + e[5]*v1.y + e[6]*v1.z + e[7]*v1.w
                + e[8]*v2.x + e[9]*v2.y + e[10]*v2.z + e[11]*v2.w
                + e[12]*v3.x + e[13]*v3.y + e[14]*v3.z + e[15]*v3.w;
        d = fmaxf(d, 0.0f);
        vals[j] = d;
        mx = fmaxf(mx, d);
    }
    #pragma unroll
    for (int o = 16; o > 0; o >>= 1) mx = fmaxf(mx, __shfl_xor_sync(0xffffffffu, mx, o));
    if ((tid & 31) == 0) redm[tid >> 5] = mx;
    __syncthreads();
    mx = redm[0];
    #pragma unroll
    for (int w = 1; w < 8; w++) mx = fmaxf(mx, redm[w]);

    float s = 0.0f;
    #pragma unroll
    for (int j = 0; j < 16; j++) { vals[j] = __expf(vals[j] - mx); s += vals[j]; }
    #pragma unroll
    for (int o = 16; o > 0; o >>= 1) s += __shfl_xor_sync(0xffffffffu, s, o);
    if ((tid & 31) == 0) reds[tid >> 5] = s;
    __syncthreads();
    s = 0.0f;
    #pragma unroll
    for (int w = 0; w < 8; w++) s += reds[w];
    float inv = 1.0f / s;
    #pragma unroll
    for (int j = 0; j < 16; j++) {
        g_Shi[(size_t)n * NN + tid + j * 256] = __float2half_rn(vals[j] * inv);
    }
}

// ================ per-node weights -> single fp16, layout [n][i][o] ==============
__global__ __launch_bounds__(256) void k_mkw(const float* __restrict__ ne,
                                             const float* __restrict__ wp,
                                             __half* __restrict__ w,
                                             int IO) {
    int io = blockIdx.x * 256 + threadIdx.x;
    float wv[EE];
    #pragma unroll
    for (int d = 0; d < EE; d++) wv[d] = wp[(size_t)d * IO + io];
    __shared__ float sne[128 * EE];
    for (int n0 = 0; n0 < NN; n0 += 128) {
        __syncthreads();
        for (int t = threadIdx.x; t < 128 * EE; t += 256) sne[t] = ne[n0 * EE + t];
        __syncthreads();
        for (int nn = 0; nn < 128; nn++) {
            float v = 0.0f;
            #pragma unroll
            for (int d = 0; d < EE; d++) v += sne[nn * EE + d] * wv[d];
            w[(size_t)(n0 + nn) * IO + io] = __float2half_rn(v);
        }
    }
}

// ================ transpose -> fp16 (hi only): B operand build ===================
__global__ __launch_bounds__(256) void k_trans(const float* __restrict__ src,
                                               __half* __restrict__ dhi,
                                               int zmul) {
    __shared__ float tile[64][68];
    int b = blockIdx.y, m0 = blockIdx.x * 64, tid = threadIdx.x;
    #pragma unroll
    for (int i = 0; i < 4; i++) {
        int id = i * 256 + tid;
        int r = id >> 4, c4 = id & 15;
        float4 v = *reinterpret_cast<const float4*>(
            src + ((size_t)b * NN + m0 + r) * 64 + c4 * 4);
        if (zmul) {
            float4 z = *reinterpret_cast<const float4*>(
                g_ZR + (size_t)(m0 + r) * XGPITCH + b * CC + c4 * 4);
            v.x *= z.x; v.y *= z.y; v.z *= z.z; v.w *= z.w;
        }
        *reinterpret_cast<float4*>(&tile[r][c4 * 4]) = v;
    }
    __syncthreads();
    int c = tid >> 2, mg = (tid & 3) * 16;
    uint32_t hi[8];
    #pragma unroll
    for (int p = 0; p < 8; p++) {
        float v0 = tile[mg + 2 * p][c], v1 = tile[mg + 2 * p + 1][c];
        __half2 hp = __floats2half2_rn(v0, v1);
        hi[p] = *reinterpret_cast<uint32_t*>(&hp);
    }
    size_t o = (size_t)(b * 64 + c) * NN + m0 + mg;
    *reinterpret_cast<uint4*>(dhi + o)     = make_uint4(hi[0], hi[1], hi[2], hi[3]);
    *reinterpret_cast<uint4*>(dhi + o + 8) = make_uint4(hi[4], hi[5], hi[6], hi[7]);
}

// ================ big GEMM via mma.sync fp16, single term ========================
// C = S @ B^T. CTA 128x128, K-chunk 64 (128B rows), 3-stage, 2 CTAs/SM.
#define OFF_B   16384
#define STAGE_BYTES 32768
#define GEMM_SMEM (3 * STAGE_BYTES)  // 96 KB

__device__ __forceinline__ uint32_t swz256(int r, int c) {
    return (uint32_t)(r * 256 + ((c ^ (r & 7)) << 4));
}
__device__ __forceinline__ uint32_t swz128(int r, int c) {
    return (uint32_t)(r * 128 + ((c ^ (r & 7)) << 4));
}

__device__ __forceinline__ void load_stage(uint32_t base, int kt, int tid,
        const __half* Ah, const __half* Bh) {
    int k0 = kt * 64;
    #pragma unroll
    for (int i = 0; i < 4; i++) {               // A & B: 128 rows x 8 chunks each
        int id = i * 256 + tid;
        int r = id >> 3, c = id & 7;
        uint32_t off = swz128(r, c);
        size_t g = (size_t)r * NN + k0 + c * 8;
        cpa16(base + off,         Ah + g);
        cpa16(base + OFF_B + off, Bh + g);
    }
    CP_COMMIT();
}

__global__ __launch_bounds__(256, 2) void k_hgemm(
        const __half* __restrict__ Bhi0,
        int coff0,
        const __half* __restrict__ Bhi1,
        int split) {
    extern __shared__ char dsm[];
    uint32_t sb = smem_u32(dsm);
    int tid = threadIdx.x, lane = tid & 31, wid = tid >> 5;
    int bn = blockIdx.x, bm = blockIdx.y;

    const __half* Bhp;
    int coff;
    if (bn < split) { Bhp = Bhi0; coff = coff0; }
    else            { Bhp = Bhi1; coff = 64; bn -= split; }

    const __half* Ah = g_Shi + (size_t)(bm * 128) * NN;
    const __half* Bh = Bhp + (size_t)(bn * 128) * NN;

    int warp_m = (wid >> 2) * 64;
    int warp_n = (wid & 3) * 32;
    float acc[4][4][4] = {};

    load_stage(sb, 0, tid, Ah, Bh);
    load_stage(sb + STAGE_BYTES, 1, tid, Ah, Bh);

    const int NKT = NN / 64;         // 64 iterations
    int lrowA = lane & 15, lgrp = lane >> 4;

    for (int kt = 0; kt < NKT; kt++) {
        CP_WAIT1();
        __syncthreads();

        if (kt + 2 < NKT)
            load_stage(sb + ((kt + 2) % 3) * STAGE_BYTES, kt + 2, tid, Ah, Bh);
        else
            CP_COMMIT();

        uint32_t base = sb + (kt % 3) * STAGE_BYTES;
        #pragma unroll
        for (int s = 0; s < 4; s++) {            // four k16 steps per 64-chunk
            int cb = s * 2 + lgrp;
            uint32_t bh[4][2];
            #pragma unroll
            for (int ng = 0; ng < 2; ng++) {
                int r = warp_n + ng * 16 + lrowA;
                uint32_t off = swz128(r, cb);
                uint32_t t0, t1, t2, t3;
                LDSM4(t0, t1, t2, t3, base + OFF_B + off);
                bh[ng * 2][0] = t0; bh[ng * 2][1] = t2;
                bh[ng * 2 + 1][0] = t1; bh[ng * 2 + 1][1] = t3;
            }
            #pragma unroll
            for (int mt = 0; mt < 4; mt++) {
                int r = warp_m + mt * 16 + lrowA;
                uint32_t off = swz128(r, cb);
                uint32_t ahi[4];
                LDSM4(ahi[0], ahi[1], ahi[2], ahi[3], base + off);
                #pragma unroll
                for (int nt = 0; nt < 4; nt++)
                    MMA_F16(acc[mt][nt], ahi, bh[nt]);
            }
        }
    }

    // epilogue: write XG as single fp16
    int row0 = bm * 128 + warp_m + (lane >> 2);
    #pragma unroll
    for (int mt = 0; mt < 4; mt++) {
        #pragma unroll
        for (int nt = 0; nt < 4; nt++) {
            int j = bn * 128 + warp_n + nt * 8 + (lane & 3) * 2;
            int b = j >> 6, c = j & 63;
            size_t p0 = (size_t)(row0 + mt * 16) * XGPITCH + b * CC + coff + c;
            size_t p1 = p0 + (size_t)8 * XGPITCH;
            __half2 h01 = __floats2half2_rn(acc[mt][nt][0], acc[mt][nt][1]);
            __half2 h23 = __floats2half2_rn(acc[mt][nt][2], acc[mt][nt][3]);
            *reinterpret_cast<__half2*>(g_XG + p0) = h01;
            *reinterpret_cast<__half2*>(g_XG + p1) = h23;
        }
    }
}

// ================ per-node gate GEMM (fp16 single-term) + sigmoid ================
#define NG_X   0
#define NG_W   16384
#define NG_BIAS 49152
#define NG_SMEM 49664

__global__ __launch_bounds__(256, 3) void k_ngate(const float* __restrict__ ne,
                                                  const float* __restrict__ gbp) {
    extern __shared__ char dsm[];
    uint32_t sb = smem_u32(dsm);
    int n = blockIdx.x, tid = threadIdx.x, lane = tid & 31, wid = tid >> 5;

    #pragma unroll
    for (int i = 0; i < 4; i++) {               // X: 64 rows x 16 chunks
        int id = i * 256 + tid;
        int r = id >> 4, c = id & 15;
        uint32_t off = swz256(r, c);
        cpa16(sb + NG_X + off, g_XG + (size_t)n * XGPITCH + r * 128 + c * 8);
    }
    #pragma unroll
    for (int i = 0; i < 8; i++) {               // W: 128 rows x 16 chunks
        int id = i * 256 + tid;
        int r = id >> 4, c = id & 15;
        uint32_t off = swz256(r, c);
        cpa16(sb + NG_W + off, g_Wg + (size_t)n * (CC * CC) + r * 128 + c * 8);
    }
    CP_COMMIT();

    if (tid < CC) {
        float v = 0.0f;
        #pragma unroll
        for (int d = 0; d < EE; d++) v += ne[n * EE + d] * gbp[d * CC + tid];
        reinterpret_cast<float*>(dsm + NG_BIAS)[tid] = v;
    }
    CP_WAIT0();
    __syncthreads();

    int warp_m = (wid >> 2) * 32;
    int warp_n = (wid & 3) * 32;
    int lrow = lane & 15, lgrp = lane >> 4;
    float acc[2][4][4] = {};

    #pragma unroll
    for (int k16 = 0; k16 < 8; k16++) {
        uint32_t bw[4][2];
        #pragma unroll
        for (int half = 0; half < 2; half++) {
            uint32_t off = swz256(k16 * 16 + lrow, (warp_n >> 3) + half * 2 + lgrp);
            uint32_t t0, t1, t2, t3;
            LDSM4T(t0, t1, t2, t3, sb + NG_W + off);
            bw[half * 2][0] = t0; bw[half * 2][1] = t1;
            bw[half * 2 + 1][0] = t2; bw[half * 2 + 1][1] = t3;
        }
        #pragma unroll
        for (int mt = 0; mt < 2; mt++) {
            uint32_t off = swz256(warp_m + mt * 16 + lrow, k16 * 2 + lgrp);
            uint32_t ah[4];
            LDSM4(ah[0], ah[1], ah[2], ah[3], sb + NG_X + off);
            #pragma unroll
            for (int nb = 0; nb < 4; nb++)
                MMA_F16(acc[mt][nb], ah, bw[nb]);
        }
    }

    const float* biasp = reinterpret_cast<const float*>(dsm + NG_BIAS);
    #pragma unroll
    for (int mt = 0; mt < 2; mt++) {
        #pragma unroll
        for (int nb = 0; nb < 4; nb++) {
            int o = warp_n + nb * 8 + (lane & 3) * 2;
            int b = warp_m + mt * 16 + (lane >> 2);
            float b0 = biasp[o], b1 = biasp[o + 1];
            float y0 = 1.0f / (1.0f + __expf(-(acc[mt][nb][0] + b0)));
            float y1 = 1.0f / (1.0f + __expf(-(acc[mt][nb][1] + b1)));
            float y2 = 1.0f / (1.0f + __expf(-(acc[mt][nb][2] + b0)));
            float y3 = 1.0f / (1.0f + __expf(-(acc[mt][nb][3] + b1)));
            *reinterpret_cast<float2*>(g_ZR + (size_t)n * XGPITCH + b * CC + o) =
                make_float2(y0, y1);
            *reinterpret_cast<float2*>(g_ZR + (size_t)n * XGPITCH + (b + 8) * CC + o) =
                make_float2(y2, y3);
        }
    }
}

// ================ per-node update GEMM (fp16 single-term) + tanh + GRU ===========
#define NF_X   0
#define NF_W   16384
#define NF_BIAS 32768
#define NF_SMEM 33280

__global__ __launch_bounds__(256, 4) void k_nfinal(const float* __restrict__ ne,
                                                   const float* __restrict__ ubp,
                                                   const float* __restrict__ st,
                                                   float* __restrict__ out) {
    extern __shared__ char dsm[];
    uint32_t sb = smem_u32(dsm);
    int n = blockIdx.x, tid = threadIdx.x, lane = tid & 31, wid = tid >> 5;

    #pragma unroll
    for (int i = 0; i < 4; i++) {               // X: 64 rows x 16 chunks
        int id = i * 256 + tid;
        int r = id >> 4, c = id & 15;
        uint32_t off = swz256(r, c);
        cpa16(sb + NF_X + off, g_XG + (size_t)n * XGPITCH + r * 128 + c * 8);
    }
    #pragma unroll
    for (int i = 0; i < 4; i++) {               // W: 128 rows x 8 chunks
        int id = i * 256 + tid;
        int r = id >> 3, c = id & 7;
        uint32_t off = swz128(r, c);
        cpa16(sb + NF_W + off, g_Wu + (size_t)n * (CC * DH) + r * 64 + c * 8);
    }
    CP_COMMIT();

    if (tid < DH) {
        float v = 0.0f;
        #pragma unroll
        for (int d = 0; d < EE; d++) v += ne[n * EE + d] * ubp[d * DH + tid];
        reinterpret_cast<float*>(dsm + NF_BIAS)[tid] = v;
    }
    CP_WAIT0();
    __syncthreads();

    int warp_m = (wid >> 2) * 32;
    int warp_n = (wid & 3) * 16;
    int lrow = lane & 15, lgrp = lane >> 4;
    float acc[2][2][4] = {};

    #pragma unroll
    for (int k16 = 0; k16 < 8; k16++) {
        uint32_t bw[2][2];
        {
            uint32_t off = swz128(k16 * 16 + lrow, (warp_n >> 3) + lgrp);
            uint32_t t0, t1, t2, t3;
            LDSM4T(t0, t1, t2, t3, sb + NF_W + off);
            bw[0][0] = t0; bw[0][1] = t1;
            bw[1][0] = t2; bw[1][1] = t3;
        }
        #pragma unroll
        for (int mt = 0; mt < 2; mt++) {
            uint32_t off = swz256(warp_m + mt * 16 + lrow, k16 * 2 + lgrp);
            uint32_t ah[4];
            LDSM4(ah[0], ah[1], ah[2], ah[3], sb + NF_X + off);
            #pragma unroll
            for (int nb = 0; nb < 2; nb++)
                MMA_F16(acc[mt][nb], ah, bw[nb]);
        }
    }

    const float* biasp = reinterpret_cast<const float*>(dsm + NF_BIAS);
    #pragma unroll
    for (int mt = 0; mt < 2; mt++) {
        #pragma unroll
        for (int nb = 0; nb < 2; nb++) {
            int o = warp_n + nb * 8 + (lane & 3) * 2;
            float b0 = biasp[o], b1 = biasp[o + 1];
            #pragma unroll
            for (int h = 0; h < 2; h++) {
                int b = warp_m + mt * 16 + (lane >> 2) + h * 8;
                float hc0 = tanhf(acc[mt][nb][h * 2] + b0);
                float hc1 = tanhf(acc[mt][nb][h * 2 + 1] + b1);
                float2 rr = *reinterpret_cast<const float2*>(
                    g_ZR + (size_t)n * XGPITCH + b * CC + DH + o);
                float2 ss = *reinterpret_cast<const float2*>(
                    st + ((size_t)b * NN + n) * DH + o);
                float2 hv;
                hv.x = rr.x * ss.x + (1.0f - rr.x) * hc0;
                hv.y = rr.y * ss.y + (1.0f - rr.y) * hc1;
                *reinterpret_cast<float2*>(out + ((size_t)b * NN + n) * DH + o) = hv;
            }
        }
    }
}

// ================ launch (multi-stream fork/join, capture-legal) =================
extern "C" void kernel_launch(void* const* d_in, const int* in_sizes, int n_in,
                              void* d_out, int out_size) {
    const float* x   = (const float*)d_in[0];
    const float* st  = (const float*)d_in[1];
    const float* ne  = (const float*)d_in[2];
    const float* gwp = (const float*)d_in[3];
    const float* gbp = (const float*)d_in[4];
    const float* uwp = (const float*)d_in[5];
    const float* ubp = (const float*)d_in[6];
    float* out = (float*)d_out;

    static cudaStream_t s1 = nullptr, s2 = nullptr;
    static cudaEvent_t e_fork, e_mkw, e_trans;
    static int initialized = 0;
    if (!initialized) {
        cudaFuncSetAttribute(k_hgemm,  cudaFuncAttributeMaxDynamicSharedMemorySize, GEMM_SMEM);
        cudaFuncSetAttribute(k_ngate,  cudaFuncAttributeMaxDynamicSharedMemorySize, NG_SMEM);
        cudaFuncSetAttribute(k_nfinal, cudaFuncAttributeMaxDynamicSharedMemorySize, NF_SMEM);
        cudaStreamCreateWithFlags(&s1, cudaStreamNonBlocking);
        cudaStreamCreateWithFlags(&s2, cudaStreamNonBlocking);
        cudaEventCreateWithFlags(&e_fork,  cudaEventDisableTiming);
        cudaEventCreateWithFlags(&e_mkw,   cudaEventDisableTiming);
        cudaEventCreateWithFlags(&e_trans, cudaEventDisableTiming);
        initialized = 1;
    }

    __half *bxh, *bsh, *wg, *wu;
    cudaGetSymbolAddress((void**)&bxh, g_BXhi);
    cudaGetSymbolAddress((void**)&bsh, g_BShi);
    cudaGetSymbolAddress((void**)&wg,  g_Wg);
    cudaGetSymbolAddress((void**)&wu,  g_Wu);

    // fork from default stream
    cudaEventRecord(e_fork, 0);
    cudaStreamWaitEvent(s1, e_fork, 0);
    cudaStreamWaitEvent(s2, e_fork, 0);

    // s1: per-node weight materialization (needed by k_ngate, much later)
    k_mkw<<<(CC * CC) / 256, 256, 0, s1>>>(ne, gwp, wg, CC * CC);
    k_mkw<<<(CC * DH) / 256, 256, 0, s1>>>(ne, uwp, wu, CC * DH);
    cudaEventRecord(e_mkw, s1);

    // s2: input transposes (needed by hgemm1), concurrent with k_supports
    k_trans<<<dim3(NN / 64, BB), 256, 0, s2>>>(x, bxh, 0);
    k_trans<<<dim3(NN / 64, BB), 256, 0, s2>>>(st, bsh, 0);
    cudaEventRecord(e_trans, s2);

    // default: supports, then join transposes before the merged GEMM
    k_supports<<<NN, 256>>>(ne);
    cudaStreamWaitEvent(0, e_trans, 0);

    // merged S@x | S@state : 2048 CTAs (128x128 tiles), 2 CTAs/SM
    k_hgemm<<<dim3(2 * NN / 128, NN / 128), 256, GEMM_SMEM>>>(
        bxh, 0, bsh, NN / 128);

    // join weights before per-node gate GEMM
    cudaStreamWaitEvent(0, e_mkw, 0);
    k_ngate<<<NN, 256, NG_SMEM>>>(ne, gbp);

    // update path
    k_trans<<<dim3(NN / 64, BB), 256>>>(st, bsh, 1);        // (z*state)^T
    k_hgemm<<<dim3(NN / 128, NN / 128), 256, GEMM_SMEM>>>(
        bsh, 64, bsh, NN / 128);
    k_nfinal<<<NN, 256, NF_SMEM>>>(ne, ubp, st, out);
}

// round 17
// speedup vs baseline: 1.4123x; 1.0029x over previous
#include <cuda_runtime.h>
#include <cuda_bf16.h>
#include <cuda_fp16.h>
#include <math.h>
#include <stdint.h>

#define NN 4096
#define BB 64
#define DIN 64
#define DH 64
#define CC 128              // DIN + DH
#define EE 16
#define XGPITCH (BB * CC)   // 8192

// ================= device scratch (no runtime allocs) ==========================
__device__ __half g_Shi[(size_t)NN * NN];            // supports fp16 (A operand)
__device__ __half g_BXhi[(size_t)NN * NN];           // x^T fp16  [j=b*64+c][m]
__device__ __half g_BShi[(size_t)NN * NN];           // state^T / (z*state)^T fp16
__device__ __half g_XG[(size_t)NN * XGPITCH];        // S@CAT fp16 [n][b*128+i]
__device__ __half g_Wg[(size_t)NN * CC * CC];        // gate W fp16 [n][i][o]
__device__ __half g_Wu[(size_t)NN * CC * DH];        // update W fp16 [n][i][o]
__device__ __half g_ZR[(size_t)NN * XGPITCH];        // z_r [n][b*128+j] fp16

// ================= PTX helpers (sm_80-level only; NO tcgen05) ====================
__device__ __forceinline__ uint32_t smem_u32(const void* p) {
    uint32_t a;
    asm("{ .reg .u64 t; cvta.to.shared.u64 t, %1; cvt.u32.u64 %0, t; }" : "=r"(a) : "l"(p));
    return a;
}
__device__ __forceinline__ void cpa16(uint32_t dst, const void* src) {
    asm volatile("cp.async.cg.shared.global [%0], [%1], 16;" :: "r"(dst), "l"(src));
}
#define CP_COMMIT() asm volatile("cp.async.commit_group;" ::: "memory")
#define CP_WAIT1()  asm volatile("cp.async.wait_group 1;" ::: "memory")
#define CP_WAIT0()  asm volatile("cp.async.wait_group 0;" ::: "memory")

#define LDSM4(r0, r1, r2, r3, addr) \
    asm volatile("ldmatrix.sync.aligned.m8n8.x4.shared.b16 {%0,%1,%2,%3}, [%4];" \
        : "=r"(r0), "=r"(r1), "=r"(r2), "=r"(r3) : "r"(addr))

#define LDSM4T(r0, r1, r2, r3, addr) \
    asm volatile("ldmatrix.sync.aligned.m8n8.x4.trans.shared.b16 {%0,%1,%2,%3}, [%4];" \
        : "=r"(r0), "=r"(r1), "=r"(r2), "=r"(r3) : "r"(addr))

#define MMA_F16(c, a, b) \
    asm volatile("mma.sync.aligned.m16n8k16.row.col.f32.f16.f16.f32 " \
        "{%0,%1,%2,%3}, {%4,%5,%6,%7}, {%8,%9}, {%0,%1,%2,%3};" \
        : "+f"((c)[0]), "+f"((c)[1]), "+f"((c)[2]), "+f"((c)[3]) \
        : "r"((a)[0]), "r"((a)[1]), "r"((a)[2]), "r"((a)[3]), \
          "r"((b)[0]), "r"((b)[1]))

// ================ supports = softmax(relu(NE @ NE^T)) -> fp16 ====================
__global__ __launch_bounds__(256) void k_supports(const float* __restrict__ ne) {
    int n = blockIdx.x, tid = threadIdx.x;
    __shared__ float e[EE];
    __shared__ float redm[8], reds[8];
    if (tid < EE) e[tid] = ne[n * EE + tid];
    __syncthreads();

    float vals[16];
    float mx = 0.0f;
    #pragma unroll
    for (int j = 0; j < 16; j++) {
        int m = tid + j * 256;
        const float4* p = reinterpret_cast<const float4*>(ne + m * EE);
        float4 v0 = p[0], v1 = p[1], v2 = p[2], v3 = p[3];
        float d = e[0]*v0.x + e[1]*v0.y + e[2]*v0.z + e[3]*v0.w
                + e[4]*v1.x + e[5]*v1.y + e[6]*v1.z + e[7]*v1.w
                + e[8]*v2.x + e[9]*v2.y + e[10]*v2.z + e[11]*v2.w
                + e[12]*v3.x + e[13]*v3.y + e[14]*v3.z + e[15]*v3.w;
        d = fmaxf(d, 0.0f);
        vals[j] = d;
        mx = fmaxf(mx, d);
    }
    #pragma unroll
    for (int o = 16; o > 0; o >>= 1) mx = fmaxf(mx, __shfl_xor_sync(0xffffffffu, mx, o));
    if ((tid & 31) == 0) redm[tid >> 5] = mx;
    __syncthreads();
    mx = redm[0];
    #pragma unroll
    for (int w = 1; w < 8; w++) mx = fmaxf(mx, redm[w]);

    float s = 0.0f;
    #pragma unroll
    for (int j = 0; j < 16; j++) { vals[j] = __expf(vals[j] - mx); s += vals[j]; }
    #pragma unroll
    for (int o = 16; o > 0; o >>= 1) s += __shfl_xor_sync(0xffffffffu, s, o);
    if ((tid & 31) == 0) reds[tid >> 5] = s;
    __syncthreads();
    s = 0.0f;
    #pragma unroll
    for (int w = 0; w < 8; w++) s += reds[w];
    float inv = 1.0f / s;
    #pragma unroll
    for (int j = 0; j < 16; j++) {
        g_Shi[(size_t)n * NN + tid + j * 256] = __float2half_rn(vals[j] * inv);
    }
}

// ================ per-node weights -> single fp16, layout [n][i][o] ==============
__global__ __launch_bounds__(256) void k_mkw(const float* __restrict__ ne,
                                             const float* __restrict__ wp,
                                             __half* __restrict__ w,
                                             int IO) {
    int io = blockIdx.x * 256 + threadIdx.x;
    float wv[EE];
    #pragma unroll
    for (int d = 0; d < EE; d++) wv[d] = wp[(size_t)d * IO + io];
    __shared__ float sne[128 * EE];
    for (int n0 = 0; n0 < NN; n0 += 128) {
        __syncthreads();
        for (int t = threadIdx.x; t < 128 * EE; t += 256) sne[t] = ne[n0 * EE + t];
        __syncthreads();
        for (int nn = 0; nn < 128; nn++) {
            float v = 0.0f;
            #pragma unroll
            for (int d = 0; d < EE; d++) v += sne[nn * EE + d] * wv[d];
            w[(size_t)(n0 + nn) * IO + io] = __float2half_rn(v);
        }
    }
}

// ================ transpose -> fp16 (hi only): B operand build ===================
__global__ __launch_bounds__(256) void k_trans(const float* __restrict__ src,
                                               __half* __restrict__ dhi,
                                               int zmul) {
    __shared__ float tile[64][68];
    int b = blockIdx.y, m0 = blockIdx.x * 64, tid = threadIdx.x;
    #pragma unroll
    for (int i = 0; i < 4; i++) {
        int id = i * 256 + tid;
        int r = id >> 4, c4 = id & 15;
        float4 v = *reinterpret_cast<const float4*>(
            src + ((size_t)b * NN + m0 + r) * 64 + c4 * 4);
        if (zmul) {
            uint2 zz = *reinterpret_cast<const uint2*>(
                g_ZR + (size_t)(m0 + r) * XGPITCH + b * CC + c4 * 4);
            __half2 z01 = *reinterpret_cast<__half2*>(&zz.x);
            __half2 z23 = *reinterpret_cast<__half2*>(&zz.y);
            v.x *= __half2float(z01.x); v.y *= __half2float(z01.y);
            v.z *= __half2float(z23.x); v.w *= __half2float(z23.y);
        }
        *reinterpret_cast<float4*>(&tile[r][c4 * 4]) = v;
    }
    __syncthreads();
    int c = tid >> 2, mg = (tid & 3) * 16;
    uint32_t hi[8];
    #pragma unroll
    for (int p = 0; p < 8; p++) {
        float v0 = tile[mg + 2 * p][c], v1 = tile[mg + 2 * p + 1][c];
        __half2 hp = __floats2half2_rn(v0, v1);
        hi[p] = *reinterpret_cast<uint32_t*>(&hp);
    }
    size_t o = (size_t)(b * 64 + c) * NN + m0 + mg;
    *reinterpret_cast<uint4*>(dhi + o)     = make_uint4(hi[0], hi[1], hi[2], hi[3]);
    *reinterpret_cast<uint4*>(dhi + o + 8) = make_uint4(hi[4], hi[5], hi[6], hi[7]);
}

// ================ big GEMM via mma.sync fp16, single term ========================
// C = S @ B^T. CTA 128x128, K-chunk 64 (128B rows), 3-stage, 2 CTAs/SM.
#define OFF_B   16384
#define STAGE_BYTES 32768
#define GEMM_SMEM (3 * STAGE_BYTES)  // 96 KB

__device__ __forceinline__ uint32_t swz256(int r, int c) {
    return (uint32_t)(r * 256 + ((c ^ (r & 7)) << 4));
}
__device__ __forceinline__ uint32_t swz128(int r, int c) {
    return (uint32_t)(r * 128 + ((c ^ (r & 7)) << 4));
}

__device__ __forceinline__ void load_stage(uint32_t base, int kt, int tid,
        const __half* Ah, const __half* Bh) {
    int k0 = kt * 64;
    #pragma unroll
    for (int i = 0; i < 4; i++) {               // A & B: 128 rows x 8 chunks each
        int id = i * 256 + tid;
        int r = id >> 3, c = id & 7;
        uint32_t off = swz128(r, c);
        size_t g = (size_t)r * NN + k0 + c * 8;
        cpa16(base + off,         Ah + g);
        cpa16(base + OFF_B + off, Bh + g);
    }
    CP_COMMIT();
}

__global__ __launch_bounds__(256, 2) void k_hgemm(
        const __half* __restrict__ Bhi0,
        int coff0,
        const __half* __restrict__ Bhi1,
        int split) {
    extern __shared__ char dsm[];
    uint32_t sb = smem_u32(dsm);
    int tid = threadIdx.x, lane = tid & 31, wid = tid >> 5;
    int bn = blockIdx.x, bm = blockIdx.y;

    const __half* Bhp;
    int coff;
    if (bn < split) { Bhp = Bhi0; coff = coff0; }
    else            { Bhp = Bhi1; coff = 64; bn -= split; }

    const __half* Ah = g_Shi + (size_t)(bm * 128) * NN;
    const __half* Bh = Bhp + (size_t)(bn * 128) * NN;

    int warp_m = (wid >> 2) * 64;
    int warp_n = (wid & 3) * 32;
    float acc[4][4][4] = {};

    load_stage(sb, 0, tid, Ah, Bh);
    load_stage(sb + STAGE_BYTES, 1, tid, Ah, Bh);

    const int NKT = NN / 64;         // 64 iterations
    int lrowA = lane & 15, lgrp = lane >> 4;

    for (int kt = 0; kt < NKT; kt++) {
        CP_WAIT1();
        __syncthreads();

        if (kt + 2 < NKT)
            load_stage(sb + ((kt + 2) % 3) * STAGE_BYTES, kt + 2, tid, Ah, Bh);
        else
            CP_COMMIT();

        uint32_t base = sb + (kt % 3) * STAGE_BYTES;
        #pragma unroll
        for (int s = 0; s < 4; s++) {            // four k16 steps per 64-chunk
            int cb = s * 2 + lgrp;
            uint32_t bh[4][2];
            #pragma unroll
            for (int ng = 0; ng < 2; ng++) {
                int r = warp_n + ng * 16 + lrowA;
                uint32_t off = swz128(r, cb);
                uint32_t t0, t1, t2, t3;
                LDSM4(t0, t1, t2, t3, base + OFF_B + off);
                bh[ng * 2][0] = t0; bh[ng * 2][1] = t2;
                bh[ng * 2 + 1][0] = t1; bh[ng * 2 + 1][1] = t3;
            }
            #pragma unroll
            for (int mt = 0; mt < 4; mt++) {
                int r = warp_m + mt * 16 + lrowA;
                uint32_t off = swz128(r, cb);
                uint32_t ahi[4];
                LDSM4(ahi[0], ahi[1], ahi[2], ahi[3], base + off);
                #pragma unroll
                for (int nt = 0; nt < 4; nt++)
                    MMA_F16(acc[mt][nt], ahi, bh[nt]);
            }
        }
    }

    // epilogue: write XG as single fp16
    int row0 = bm * 128 + warp_m + (lane >> 2);
    #pragma unroll
    for (int mt = 0; mt < 4; mt++) {
        #pragma unroll
        for (int nt = 0; nt < 4; nt++) {
            int j = bn * 128 + warp_n + nt * 8 + (lane & 3) * 2;
            int b = j >> 6, c = j & 63;
            size_t p0 = (size_t)(row0 + mt * 16) * XGPITCH + b * CC + coff + c;
            size_t p1 = p0 + (size_t)8 * XGPITCH;
            __half2 h01 = __floats2half2_rn(acc[mt][nt][0], acc[mt][nt][1]);
            __half2 h23 = __floats2half2_rn(acc[mt][nt][2], acc[mt][nt][3]);
            *reinterpret_cast<__half2*>(g_XG + p0) = h01;
            *reinterpret_cast<__half2*>(g_XG + p1) = h23;
        }
    }
}

// ================ per-node gate GEMM (fp16 single-term) + sigmoid ================
#define NG_X   0
#define NG_W   16384
#define NG_BIAS 49152
#define NG_SMEM 49664

__global__ __launch_bounds__(256, 3) void k_ngate(const float* __restrict__ ne,
                                                  const float* __restrict__ gbp) {
    extern __shared__ char dsm[];
    uint32_t sb = smem_u32(dsm);
    int n = blockIdx.x, tid = threadIdx.x, lane = tid & 31, wid = tid >> 5;

    #pragma unroll
    for (int i = 0; i < 4; i++) {               // X: 64 rows x 16 chunks
        int id = i * 256 + tid;
        int r = id >> 4, c = id & 15;
        uint32_t off = swz256(r, c);
        cpa16(sb + NG_X + off, g_XG + (size_t)n * XGPITCH + r * 128 + c * 8);
    }
    #pragma unroll
    for (int i = 0; i < 8; i++) {               // W: 128 rows x 16 chunks
        int id = i * 256 + tid;
        int r = id >> 4, c = id & 15;
        uint32_t off = swz256(r, c);
        cpa16(sb + NG_W + off, g_Wg + (size_t)n * (CC * CC) + r * 128 + c * 8);
    }
    CP_COMMIT();

    if (tid < CC) {
        float v = 0.0f;
        #pragma unroll
        for (int d = 0; d < EE; d++) v += ne[n * EE + d] * gbp[d * CC + tid];
        reinterpret_cast<float*>(dsm + NG_BIAS)[tid] = v;
    }
    CP_WAIT0();
    __syncthreads();

    int warp_m = (wid >> 2) * 32;
    int warp_n = (wid & 3) * 32;
    int lrow = lane & 15, lgrp = lane >> 4;
    float acc[2][4][4] = {};

    #pragma unroll
    for (int k16 = 0; k16 < 8; k16++) {
        uint32_t bw[4][2];
        #pragma unroll
        for (int half = 0; half < 2; half++) {
            uint32_t off = swz256(k16 * 16 + lrow, (warp_n >> 3) + half * 2 + lgrp);
            uint32_t t0, t1, t2, t3;
            LDSM4T(t0, t1, t2, t3, sb + NG_W + off);
            bw[half * 2][0] = t0; bw[half * 2][1] = t1;
            bw[half * 2 + 1][0] = t2; bw[half * 2 + 1][1] = t3;
        }
        #pragma unroll
        for (int mt = 0; mt < 2; mt++) {
            uint32_t off = swz256(warp_m + mt * 16 + lrow, k16 * 2 + lgrp);
            uint32_t ah[4];
            LDSM4(ah[0], ah[1], ah[2], ah[3], sb + NG_X + off);
            #pragma unroll
            for (int nb = 0; nb < 4; nb++)
                MMA_F16(acc[mt][nb], ah, bw[nb]);
        }
    }

    const float* biasp = reinterpret_cast<const float*>(dsm + NG_BIAS);
    #pragma unroll
    for (int mt = 0; mt < 2; mt++) {
        #pragma unroll
        for (int nb = 0; nb < 4; nb++) {
            int o = warp_n + nb * 8 + (lane & 3) * 2;
            int b = warp_m + mt * 16 + (lane >> 2);
            float b0 = biasp[o], b1 = biasp[o + 1];
            float y0 = 1.0f / (1.0f + __expf(-(acc[mt][nb][0] + b0)));
            float y1 = 1.0f / (1.0f + __expf(-(acc[mt][nb][1] + b1)));
            float y2 = 1.0f / (1.0f + __expf(-(acc[mt][nb][2] + b0)));
            float y3 = 1.0f / (1.0f + __expf(-(acc[mt][nb][3] + b1)));
            *reinterpret_cast<__half2*>(g_ZR + (size_t)n * XGPITCH + b * CC + o) =
                __floats2half2_rn(y0, y1);
            *reinterpret_cast<__half2*>(g_ZR + (size_t)n * XGPITCH + (b + 8) * CC + o) =
                __floats2half2_rn(y2, y3);
        }
    }
}

// ================ per-node update GEMM (fp16 single-term) + tanh + GRU ===========
#define NF_X   0
#define NF_W   16384
#define NF_BIAS 32768
#define NF_SMEM 33280

__global__ __launch_bounds__(256, 4) void k_nfinal(const float* __restrict__ ne,
                                                   const float* __restrict__ ubp,
                                                   const float* __restrict__ st,
                                                   float* __restrict__ out) {
    extern __shared__ char dsm[];
    uint32_t sb = smem_u32(dsm);
    int n = blockIdx.x, tid = threadIdx.x, lane = tid & 31, wid = tid >> 5;

    #pragma unroll
    for (int i = 0; i < 4; i++) {               // X: 64 rows x 16 chunks
        int id = i * 256 + tid;
        int r = id >> 4, c = id & 15;
        uint32_t off = swz256(r, c);
        cpa16(sb + NF_X + off, g_XG + (size_t)n * XGPITCH + r * 128 + c * 8);
    }
    #pragma unroll
    for (int i = 0; i < 4; i++) {               // W: 128 rows x 8 chunks
        int id = i * 256 + tid;
        int r = id >> 3, c = id & 7;
        uint32_t off = swz128(r, c);
        cpa16(sb + NF_W + off, g_Wu + (size_t)n * (CC * DH) + r * 64 + c * 8);
    }
    CP_COMMIT();

    if (tid < DH) {
        float v = 0.0f;
        #pragma unroll
        for (int d = 0; d < EE; d++) v += ne[n * EE + d] * ubp[d * DH + tid];
        reinterpret_cast<float*>(dsm + NF_BIAS)[tid] = v;
    }
    CP_WAIT0();
    __syncthreads();

    int warp_m = (wid >> 2) * 32;
    int warp_n = (wid & 3) * 16;
    int lrow = lane & 15, lgrp = lane >> 4;
    float acc[2][2][4] = {};

    #pragma unroll
    for (int k16 = 0; k16 < 8; k16++) {
        uint32_t bw[2][2];
        {
            uint32_t off = swz128(k16 * 16 + lrow, (warp_n >> 3) + lgrp);
            uint32_t t0, t1, t2, t3;
            LDSM4T(t0, t1, t2, t3, sb + NF_W + off);
            bw[0][0] = t0; bw[0][1] = t1;
            bw[1][0] = t2; bw[1][1] = t3;
        }
        #pragma unroll
        for (int mt = 0; mt < 2; mt++) {
            uint32_t off = swz256(warp_m + mt * 16 + lrow, k16 * 2 + lgrp);
            uint32_t ah[4];
            LDSM4(ah[0], ah[1], ah[2], ah[3], sb + NF_X + off);
            #pragma unroll
            for (int nb = 0; nb < 2; nb++)
                MMA_F16(acc[mt][nb], ah, bw[nb]);
        }
    }

    const float* biasp = reinterpret_cast<const float*>(dsm + NF_BIAS);
    #pragma unroll
    for (int mt = 0; mt < 2; mt++) {
        #pragma unroll
        for (int nb = 0; nb < 2; nb++) {
            int o = warp_n + nb * 8 + (lane & 3) * 2;
            float b0 = biasp[o], b1 = biasp[o + 1];
            #pragma unroll
            for (int h = 0; h < 2; h++) {
                int b = warp_m + mt * 16 + (lane >> 2) + h * 8;
                float hc0 = tanhf(acc[mt][nb][h * 2] + b0);
                float hc1 = tanhf(acc[mt][nb][h * 2 + 1] + b1);
                __half2 rr2 = *reinterpret_cast<const __half2*>(
                    g_ZR + (size_t)n * XGPITCH + b * CC + DH + o);
                float2 ss = *reinterpret_cast<const float2*>(
                    st + ((size_t)b * NN + n) * DH + o);
                float r0 = __half2float(rr2.x), r1 = __half2float(rr2.y);
                float2 hv;
                hv.x = r0 * ss.x + (1.0f - r0) * hc0;
                hv.y = r1 * ss.y + (1.0f - r1) * hc1;
                *reinterpret_cast<float2*>(out + ((size_t)b * NN + n) * DH + o) = hv;
            }
        }
    }
}

// ================ launch (multi-stream fork/join, capture-legal) =================
extern "C" void kernel_launch(void* const* d_in, const int* in_sizes, int n_in,
                              void* d_out, int out_size) {
    const float* x   = (const float*)d_in[0];
    const float* st  = (const float*)d_in[1];
    const float* ne  = (const float*)d_in[2];
    const float* gwp = (const float*)d_in[3];
    const float* gbp = (const float*)d_in[4];
    const float* uwp = (const float*)d_in[5];
    const float* ubp = (const float*)d_in[6];
    float* out = (float*)d_out;

    static cudaStream_t s1 = nullptr, s2 = nullptr;
    static cudaEvent_t e_fork, e_mkw, e_trans;
    static int initialized = 0;
    if (!initialized) {
        cudaFuncSetAttribute(k_hgemm,  cudaFuncAttributeMaxDynamicSharedMemorySize, GEMM_SMEM);
        cudaFuncSetAttribute(k_ngate,  cudaFuncAttributeMaxDynamicSharedMemorySize, NG_SMEM);
        cudaFuncSetAttribute(k_nfinal, cudaFuncAttributeMaxDynamicSharedMemorySize, NF_SMEM);
        cudaStreamCreateWithFlags(&s1, cudaStreamNonBlocking);
        cudaStreamCreateWithFlags(&s2, cudaStreamNonBlocking);
        cudaEventCreateWithFlags(&e_fork,  cudaEventDisableTiming);
        cudaEventCreateWithFlags(&e_mkw,   cudaEventDisableTiming);
        cudaEventCreateWithFlags(&e_trans, cudaEventDisableTiming);
        initialized = 1;
    }

    __half *bxh, *bsh, *wg, *wu;
    cudaGetSymbolAddress((void**)&bxh, g_BXhi);
    cudaGetSymbolAddress((void**)&bsh, g_BShi);
    cudaGetSymbolAddress((void**)&wg,  g_Wg);
    cudaGetSymbolAddress((void**)&wu,  g_Wu);

    // fork from default stream
    cudaEventRecord(e_fork, 0);
    cudaStreamWaitEvent(s1, e_fork, 0);
    cudaStreamWaitEvent(s2, e_fork, 0);

    // s1: per-node weight materialization (needed by k_ngate, much later)
    k_mkw<<<(CC * CC) / 256, 256, 0, s1>>>(ne, gwp, wg, CC * CC);
    k_mkw<<<(CC * DH) / 256, 256, 0, s1>>>(ne, uwp, wu, CC * DH);
    cudaEventRecord(e_mkw, s1);

    // s2: input transposes (needed by hgemm1), concurrent with k_supports
    k_trans<<<dim3(NN / 64, BB), 256, 0, s2>>>(x, bxh, 0);
    k_trans<<<dim3(NN / 64, BB), 256, 0, s2>>>(st, bsh, 0);
    cudaEventRecord(e_trans, s2);

    // default: supports, then join transposes before the merged GEMM
    k_supports<<<NN, 256>>>(ne);
    cudaStreamWaitEvent(0, e_trans, 0);

    // merged S@x | S@state : 2048 CTAs (128x128 tiles), 2 CTAs/SM
    k_hgemm<<<dim3(2 * NN / 128, NN / 128), 256, GEMM_SMEM>>>(
        bxh, 0, bsh, NN / 128);

    // join weights before per-node gate GEMM
    cudaStreamWaitEvent(0, e_mkw, 0);
    k_ngate<<<NN, 256, NG_SMEM>>>(ne, gbp);

    // update path
    k_trans<<<dim3(NN / 64, BB), 256>>>(st, bsh, 1);        // (z*state)^T
    k_hgemm<<<dim3(NN / 128, NN / 128), 256, GEMM_SMEM>>>(
        bsh, 64, bsh, NN / 128);
    k_nfinal<<<NN, 256, NF_SMEM>>>(ne, ubp, st, out);
}